// round 1
// baseline (speedup 1.0000x reference)
#include <cuda_runtime.h>
#include <math.h>

#define Bb_ 4
#define S_ 1024
#define HID_ 4096
#define NH_ 32
#define HD_ 128
#define O3_ 12288
#define R_ 32
#define SCALE_ 0.08838834764831845f

// ---- scratch (static device globals; no runtime allocation) ----
__device__ float g_qkv[(size_t)Bb_ * S_ * O3_];        // 201 MB
__device__ float g_mid[Bb_ * S_ * R_];                 // lora mid
__device__ float g_q[(size_t)Bb_ * NH_ * S_ * HD_];    // 67 MB (post-rope)
__device__ float g_k[(size_t)Bb_ * NH_ * S_ * HD_];    // 67 MB (post-rope)
__device__ float g_scores[(size_t)Bb_ * NH_ * S_ * S_];// 512 MB
__device__ float g_attn[(size_t)Bb_ * S_ * HID_];      // 67 MB

// ---- GEMM tiling ----
#define BM 128
#define BN 128
#define BK 16
#define SMP 132   // padded smem row (16B-aligned rows, reduced bank conflicts)

// NT GEMM: C[m,n] = sum_k A[m*K+k] * B[n*K+k].  M,N multiples of 128; K mult of 16.
template<bool LORA, bool SCALEOUT>
__device__ __forceinline__ void gemm_nt_dev(
    const float* __restrict__ A, const float* __restrict__ Bm,
    float* __restrict__ C, int N, int K,
    const float* __restrict__ lora_out, const float* __restrict__ mid)
{
    __shared__ float As[BK][SMP];
    __shared__ float Bs[BK][SMP];
    const int bm = blockIdx.y, bn = blockIdx.x;
    const int tid = threadIdx.x;
    const int tr = tid >> 4, tc = tid & 15;
    const int lr = tid >> 2;
    const int lq = (tid & 3) << 2;

    float acc[8][8];
#pragma unroll
    for (int i = 0; i < 8; i++)
#pragma unroll
        for (int j = 0; j < 8; j++) acc[i][j] = 0.f;

    const float* Ab = A + (size_t)bm * BM * K;
    const float* Bp = Bm + (size_t)bn * BN * K;

    for (int k0 = 0; k0 < K; k0 += BK) {
#pragma unroll
        for (int rr = 0; rr < 2; rr++) {
            int m = lr + rr * 64;
            float4 va = *reinterpret_cast<const float4*>(Ab + (size_t)m * K + k0 + lq);
            As[lq + 0][m] = va.x; As[lq + 1][m] = va.y;
            As[lq + 2][m] = va.z; As[lq + 3][m] = va.w;
            float4 vb = *reinterpret_cast<const float4*>(Bp + (size_t)m * K + k0 + lq);
            Bs[lq + 0][m] = vb.x; Bs[lq + 1][m] = vb.y;
            Bs[lq + 2][m] = vb.z; Bs[lq + 3][m] = vb.w;
        }
        __syncthreads();
#pragma unroll
        for (int kk = 0; kk < BK; kk++) {
            float4 a0 = *reinterpret_cast<const float4*>(&As[kk][tr * 8]);
            float4 a1 = *reinterpret_cast<const float4*>(&As[kk][tr * 8 + 4]);
            float4 b0 = *reinterpret_cast<const float4*>(&Bs[kk][tc * 8]);
            float4 b1 = *reinterpret_cast<const float4*>(&Bs[kk][tc * 8 + 4]);
            float a[8] = {a0.x, a0.y, a0.z, a0.w, a1.x, a1.y, a1.z, a1.w};
            float b[8] = {b0.x, b0.y, b0.z, b0.w, b1.x, b1.y, b1.z, b1.w};
#pragma unroll
            for (int i = 0; i < 8; i++)
#pragma unroll
                for (int j = 0; j < 8; j++) acc[i][j] = fmaf(a[i], b[j], acc[i][j]);
        }
        __syncthreads();
    }

    const int row0 = bm * BM + tr * 8;
    const int col0 = bn * BN + tc * 8;

    if (LORA) {
        const int b = row0 / S_;   // BM divides S_, so one batch per 8-row strip
#pragma unroll 4
        for (int r = 0; r < R_; r++) {
            float mr[8], lc[8];
#pragma unroll
            for (int i = 0; i < 8; i++) mr[i] = mid[(size_t)(row0 + i) * R_ + r];
#pragma unroll
            for (int j = 0; j < 8; j++)
                lc[j] = lora_out[((size_t)b * O3_ + col0 + j) * R_ + r];
#pragma unroll
            for (int i = 0; i < 8; i++)
#pragma unroll
                for (int j = 0; j < 8; j++) acc[i][j] = fmaf(mr[i], lc[j], acc[i][j]);
        }
    }
    if (SCALEOUT) {
#pragma unroll
        for (int i = 0; i < 8; i++)
#pragma unroll
            for (int j = 0; j < 8; j++) acc[i][j] *= SCALE_;
    }
#pragma unroll
    for (int i = 0; i < 8; i++) {
        float4 c0 = make_float4(acc[i][0], acc[i][1], acc[i][2], acc[i][3]);
        float4 c1 = make_float4(acc[i][4], acc[i][5], acc[i][6], acc[i][7]);
        *reinterpret_cast<float4*>(C + (size_t)(row0 + i) * N + col0) = c0;
        *reinterpret_cast<float4*>(C + (size_t)(row0 + i) * N + col0 + 4) = c1;
    }
}

// ---- kernel 1: lora_mid[b,s,r] = hs[b,s,:] . lora_in[b,r,:] ----
__global__ __launch_bounds__(256) void lora_mid_kernel(
    const float* __restrict__ hs, const float* __restrict__ lin)
{
    const int row = blockIdx.x;             // b*S + s
    const int b = row / S_;
    __shared__ float sh[HID_];
    for (int i = threadIdx.x; i < HID_; i += 256) sh[i] = hs[(size_t)row * HID_ + i];
    __syncthreads();
    const int warp = threadIdx.x >> 5, lane = threadIdx.x & 31;
    for (int r = warp; r < R_; r += 8) {
        const float* lrow = lin + ((size_t)b * R_ + r) * HID_;
        float acc = 0.f;
        for (int i = lane; i < HID_; i += 32) acc = fmaf(sh[i], lrow[i], acc);
#pragma unroll
        for (int o = 16; o > 0; o >>= 1) acc += __shfl_xor_sync(0xffffffffu, acc, o);
        if (lane == 0) g_mid[(size_t)row * R_ + r] = acc;
    }
}

// ---- kernel 2: QKV projection + lora epilogue ----
__global__ __launch_bounds__(256) void qkv_gemm_kernel(
    const float* __restrict__ hs, const float* __restrict__ w,
    const float* __restrict__ lora_out)
{
    gemm_nt_dev<true, false>(hs, w, g_qkv, O3_, HID_, lora_out, g_mid);
}

// ---- kernel 3: rope on q,k; write (b,h,s,d) ----
__global__ __launch_bounds__(256) void rope_kernel(const int* __restrict__ positions)
{
    const int bs = blockIdx.x;
    const int b = bs / S_, s = bs % S_;
    __shared__ float cs[64], sn[64];
    if (threadIdx.x < 64) {
        float inv = powf(10000.f, -(float)threadIdx.x / 64.f);
        float f = (float)positions[s] * inv;
        cs[threadIdx.x] = cosf(f);
        sn[threadIdx.x] = sinf(f);
    }
    __syncthreads();
    const float* base = g_qkv + (size_t)bs * O3_;
    for (int t = threadIdx.x; t < NH_ * 64; t += 256) {
        int h = t >> 6, i = t & 63;
        float c = cs[i], sv = sn[i];
        size_t o = ((size_t)(b * NH_ + h) * S_ + s) * HD_;
        float x1 = base[h * HD_ + i], x2 = base[h * HD_ + 64 + i];
        g_q[o + i]      = x1 * c - x2 * sv;
        g_q[o + 64 + i] = x2 * c + x1 * sv;
        float y1 = base[HID_ + h * HD_ + i], y2 = base[HID_ + h * HD_ + 64 + i];
        g_k[o + i]      = y1 * c - y2 * sv;
        g_k[o + 64 + i] = y2 * c + y1 * sv;
    }
}

// ---- kernel 4: scores = scale * q k^T  (causal: skip fully-masked tiles) ----
__global__ __launch_bounds__(256) void scores_kernel()
{
    if (blockIdx.x > blockIdx.y) return;   // tile entirely above diagonal
    const int z = blockIdx.z;
    const float* A = g_q + (size_t)z * S_ * HD_;
    const float* Bp = g_k + (size_t)z * S_ * HD_;
    float* C = g_scores + (size_t)z * S_ * S_;
    gemm_nt_dev<false, true>(A, Bp, C, S_, HD_, nullptr, nullptr);
}

// ---- kernel 5: causal row softmax (writes 0 for k > q) ----
__global__ __launch_bounds__(256) void softmax_kernel()
{
    const size_t row = blockIdx.x;              // z*S + q
    const int q = (int)(row & (S_ - 1));
    float* p = g_scores + row * S_;
    const int n = q + 1;
    const int tid = threadIdx.x;
    __shared__ float red[8];

    float m = -1e30f;
    for (int i = tid; i < n; i += 256) m = fmaxf(m, p[i]);
#pragma unroll
    for (int o = 16; o > 0; o >>= 1) m = fmaxf(m, __shfl_xor_sync(0xffffffffu, m, o));
    if ((tid & 31) == 0) red[tid >> 5] = m;
    __syncthreads();
    float mm = red[0];
#pragma unroll
    for (int i = 1; i < 8; i++) mm = fmaxf(mm, red[i]);

    float sum = 0.f;
    for (int i = tid; i < n; i += 256) {
        float e = __expf(p[i] - mm);
        p[i] = e;
        sum += e;
    }
#pragma unroll
    for (int o = 16; o > 0; o >>= 1) sum += __shfl_xor_sync(0xffffffffu, sum, o);
    __syncthreads();
    if ((tid & 31) == 0) red[tid >> 5] = sum;
    __syncthreads();
    float tot = 0.f;
#pragma unroll
    for (int i = 0; i < 8; i++) tot += red[i];
    float inv = 1.f / tot;
    for (int i = tid; i < n; i += 256) p[i] *= inv;
    for (int i = n + tid; i < S_; i += 256) p[i] = 0.f;
}

// ---- kernel 6: attn = probs @ V   (V read in-place from g_qkv; NN form) ----
__global__ __launch_bounds__(256) void pv_kernel()
{
    const int z = blockIdx.y;                   // b*NH + h
    const int bq = blockIdx.x;                  // q tile
    const int b = z >> 5, h = z & 31;
    const float* A = g_scores + (size_t)z * S_ * S_;
    const float* Bv = g_qkv + (size_t)b * S_ * O3_ + 2 * HID_ + h * HD_;
    float* C = g_attn + ((size_t)b * S_ + (size_t)bq * BM) * HID_ + h * HD_;

    __shared__ float As[BK][SMP];
    __shared__ float Bs[BK][SMP];
    const int tid = threadIdx.x;
    const int tr = tid >> 4, tc = tid & 15;
    const int lr = tid >> 2, lq = (tid & 3) << 2;
    const int kr = tid >> 4;                    // 0..15 (B tile rows)
    const int nq = (tid & 15) << 3;             // 0..120 step 8

    float acc[8][8];
#pragma unroll
    for (int i = 0; i < 8; i++)
#pragma unroll
        for (int j = 0; j < 8; j++) acc[i][j] = 0.f;

    int kmax = (bq + 1) * BM;
    if (kmax > S_) kmax = S_;
    const float* Ab = A + (size_t)bq * BM * S_;

    for (int k0 = 0; k0 < kmax; k0 += BK) {
#pragma unroll
        for (int rr = 0; rr < 2; rr++) {
            int m = lr + rr * 64;
            float4 va = *reinterpret_cast<const float4*>(Ab + (size_t)m * S_ + k0 + lq);
            As[lq + 0][m] = va.x; As[lq + 1][m] = va.y;
            As[lq + 2][m] = va.z; As[lq + 3][m] = va.w;
        }
        {
            const float* brow = Bv + (size_t)(k0 + kr) * O3_ + nq;
            float4 vb0 = *reinterpret_cast<const float4*>(brow);
            float4 vb1 = *reinterpret_cast<const float4*>(brow + 4);
            *reinterpret_cast<float4*>(&Bs[kr][nq]) = vb0;
            *reinterpret_cast<float4*>(&Bs[kr][nq + 4]) = vb1;
        }
        __syncthreads();
#pragma unroll
        for (int kk = 0; kk < BK; kk++) {
            float4 a0 = *reinterpret_cast<const float4*>(&As[kk][tr * 8]);
            float4 a1 = *reinterpret_cast<const float4*>(&As[kk][tr * 8 + 4]);
            float4 b0 = *reinterpret_cast<const float4*>(&Bs[kk][tc * 8]);
            float4 b1 = *reinterpret_cast<const float4*>(&Bs[kk][tc * 8 + 4]);
            float a[8] = {a0.x, a0.y, a0.z, a0.w, a1.x, a1.y, a1.z, a1.w};
            float bv[8] = {b0.x, b0.y, b0.z, b0.w, b1.x, b1.y, b1.z, b1.w};
#pragma unroll
            for (int i = 0; i < 8; i++)
#pragma unroll
                for (int j = 0; j < 8; j++) acc[i][j] = fmaf(a[i], bv[j], acc[i][j]);
        }
        __syncthreads();
    }
#pragma unroll
    for (int i = 0; i < 8; i++) {
        float* crow = C + (size_t)(tr * 8 + i) * HID_ + tc * 8;
        float4 c0 = make_float4(acc[i][0], acc[i][1], acc[i][2], acc[i][3]);
        float4 c1 = make_float4(acc[i][4], acc[i][5], acc[i][6], acc[i][7]);
        *reinterpret_cast<float4*>(crow) = c0;
        *reinterpret_cast<float4*>(crow + 4) = c1;
    }
}

// ---- kernel 7: out = attn @ w_dense^T ----
__global__ __launch_bounds__(256) void dense_gemm_kernel(
    const float* __restrict__ w, float* __restrict__ out)
{
    gemm_nt_dev<false, false>(g_attn, w, out, HID_, HID_, nullptr, nullptr);
}

extern "C" void kernel_launch(void* const* d_in, const int* in_sizes, int n_in,
                              void* d_out, int out_size)
{
    const int*   positions = (const int*)d_in[0];
    const float* hs        = (const float*)d_in[1];
    const float* w_qkv     = (const float*)d_in[2];
    const float* w_dense   = (const float*)d_in[3];
    const float* lora_in   = (const float*)d_in[4];
    const float* lora_out  = (const float*)d_in[5];
    float* out = (float*)d_out;

    lora_mid_kernel<<<Bb_ * S_, 256>>>(hs, lora_in);

    dim3 gq(O3_ / BN, (Bb_ * S_) / BM);
    qkv_gemm_kernel<<<gq, 256>>>(hs, w_qkv, lora_out);

    rope_kernel<<<Bb_ * S_, 256>>>(positions);

    dim3 gs(S_ / BN, S_ / BM, Bb_ * NH_);
    scores_kernel<<<gs, 256>>>();

    softmax_kernel<<<Bb_ * NH_ * S_, 256>>>();

    dim3 gp(S_ / BM, Bb_ * NH_);
    pv_kernel<<<gp, 256>>>();

    dim3 gd(HID_ / BN, (Bb_ * S_) / BM);
    dense_gemm_kernel<<<gd, 256>>>(w_dense, out);
}

// round 5
// speedup vs baseline: 1.8911x; 1.8911x over previous
#include <cuda_runtime.h>
#include <cuda_bf16.h>
#include <mma.h>
#include <math.h>
#include <stdint.h>
#include <type_traits>

using namespace nvcuda;

#define Bb_ 4
#define S_ 1024
#define HID_ 4096
#define NH_ 32
#define HD_ 128
#define O3_ 12288
#define R_ 32
#define SCALE_ 0.08838834764831845f

typedef __nv_bfloat16 bf16;

// ---- scratch: EXACTLY the R1-proven buffer set (914 MB) ----
__device__ float g_qkv[(size_t)Bb_ * S_ * O3_];        // 201 MB
__device__ float g_mid[Bb_ * S_ * R_];
__device__ float g_q[(size_t)Bb_ * NH_ * S_ * HD_];    // 67 MB
__device__ float g_k[(size_t)Bb_ * NH_ * S_ * HD_];    // 67 MB
__device__ float g_scores[(size_t)Bb_ * NH_ * S_ * S_];// 512 MB
__device__ float g_attn[(size_t)Bb_ * S_ * HID_];      // 67 MB

__device__ __forceinline__ void split1(float x, bf16& h, bf16& l) {
    h = __float2bfloat16(x);
    l = __float2bfloat16(x - __bfloat162float(h));
}

// ---------------- wmma split GEMM core ----------------
// C[m,n] = A[m,:].B'  where B' is B[n][k] (BROW=0, NT) or B[k][n] (BROW=1, NN).
// fp32 inputs split in-kernel to bf16 hi/lo; 3-term MMA; fp32 accum/output.
// Block tile 128x128, 8 warps (2x4), warp tile 64x32, BK=16 per iteration.
template <int BROW, int LORA, int SCALEOUT>
__device__ __forceinline__ void gemm_wmma_core(
    const float* __restrict__ A, const int lda,
    const float* __restrict__ B, const int ldb,
    float* __restrict__ C, const int ldc,
    const int klim, const int bm, const int bn,
    const float* __restrict__ mid, const float* __restrict__ lora)
{
    __shared__ __align__(16) bf16 smA[2][128][24];                  // [hi/lo][m][k] 12KB
    constexpr int BSZ = BROW ? (2 * 16 * 136) : (2 * 128 * 24);
    __shared__ __align__(16) bf16 smB[BSZ];                         // 8.5KB or 12KB

    const int t = threadIdx.x;
    const int lane = t & 31, warp = t >> 5;
    const int wm = warp >> 2, wn = warp & 3;
    (void)lane;

    wmma::fragment<wmma::accumulator, 16, 16, 16, float> cfr[4][2];
#pragma unroll
    for (int mi = 0; mi < 4; mi++)
#pragma unroll
        for (int ni = 0; ni < 2; ni++) wmma::fill_fragment(cfr[mi][ni], 0.0f);

    const int kT = klim >> 4;
    const int total = kT + (LORA ? (R_ / 16) : 0);

    for (int tt = 0; tt < total; tt++) {
        const bool tail = LORA && (tt >= kT);
        const int k0 = tail ? ((tt - kT) << 4) : (tt << 4);
        __syncthreads();
        // ---- A tile: 128x16 fp32 -> split -> smA hi/lo ----
#pragma unroll
        for (int i = 0; i < 2; i++) {
            int idx = i * 256 + t;            // 0..511
            int row = idx >> 2, q4 = (idx & 3) * 4;
            const float* src = tail
                ? (mid + (size_t)(bm * 128 + row) * R_ + k0 + q4)
                : (A + (size_t)(bm * 128 + row) * lda + k0 + q4);
            float4 v = *reinterpret_cast<const float4*>(src);
            split1(v.x, smA[0][row][q4 + 0], smA[1][row][q4 + 0]);
            split1(v.y, smA[0][row][q4 + 1], smA[1][row][q4 + 1]);
            split1(v.z, smA[0][row][q4 + 2], smA[1][row][q4 + 2]);
            split1(v.w, smA[0][row][q4 + 3], smA[1][row][q4 + 3]);
        }
        // ---- B tile ----
#pragma unroll
        for (int i = 0; i < 2; i++) {
            int idx = i * 256 + t;
            if (!BROW || tail) {
                // [n][k] source (lora tail is also [n][k] with ld=R_)
                int row = idx >> 2, q4 = (idx & 3) * 4;
                const float* src = tail
                    ? (lora + (size_t)(bn * 128 + row) * R_ + k0 + q4)
                    : (B + (size_t)(bn * 128 + row) * ldb + k0 + q4);
                float4 v = *reinterpret_cast<const float4*>(src);
                if (!BROW) {
                    split1(v.x, smB[row * 24 + q4 + 0], smB[128 * 24 + row * 24 + q4 + 0]);
                    split1(v.y, smB[row * 24 + q4 + 1], smB[128 * 24 + row * 24 + q4 + 1]);
                    split1(v.z, smB[row * 24 + q4 + 2], smB[128 * 24 + row * 24 + q4 + 2]);
                    split1(v.w, smB[row * 24 + q4 + 3], smB[128 * 24 + row * 24 + q4 + 3]);
                }
            } else {
                // [k][n] source
                int kr = idx >> 5, nc = (idx & 31) * 4;
                const float* src = B + (size_t)(k0 + kr) * ldb + bn * 128 + nc;
                float4 v = *reinterpret_cast<const float4*>(src);
                split1(v.x, smB[kr * 136 + nc + 0], smB[16 * 136 + kr * 136 + nc + 0]);
                split1(v.y, smB[kr * 136 + nc + 1], smB[16 * 136 + kr * 136 + nc + 1]);
                split1(v.z, smB[kr * 136 + nc + 2], smB[16 * 136 + kr * 136 + nc + 2]);
                split1(v.w, smB[kr * 136 + nc + 3], smB[16 * 136 + kr * 136 + nc + 3]);
            }
        }
        __syncthreads();

        using BLay = typename std::conditional<BROW != 0, wmma::row_major, wmma::col_major>::type;
        wmma::fragment<wmma::matrix_b, 16, 16, 16, bf16, BLay> bH[2], bL[2];
#pragma unroll
        for (int ni = 0; ni < 2; ni++) {
            if (BROW) {
                wmma::load_matrix_sync(bH[ni], &smB[wn * 32 + ni * 16], 136);
                wmma::load_matrix_sync(bL[ni], &smB[16 * 136 + wn * 32 + ni * 16], 136);
            } else {
                wmma::load_matrix_sync(bH[ni], &smB[(wn * 32 + ni * 16) * 24], 24);
                wmma::load_matrix_sync(bL[ni], &smB[128 * 24 + (wn * 32 + ni * 16) * 24], 24);
            }
        }
#pragma unroll
        for (int mi = 0; mi < 4; mi++) {
            wmma::fragment<wmma::matrix_a, 16, 16, 16, bf16, wmma::row_major> aH, aL;
            wmma::load_matrix_sync(aH, &smA[0][wm * 64 + mi * 16][0], 24);
            wmma::load_matrix_sync(aL, &smA[1][wm * 64 + mi * 16][0], 24);
#pragma unroll
            for (int ni = 0; ni < 2; ni++) {
                wmma::mma_sync(cfr[mi][ni], aH, bH[ni], cfr[mi][ni]);
                wmma::mma_sync(cfr[mi][ni], aH, bL[ni], cfr[mi][ni]);
                wmma::mma_sync(cfr[mi][ni], aL, bH[ni], cfr[mi][ni]);
            }
        }
    }

#pragma unroll
    for (int mi = 0; mi < 4; mi++)
#pragma unroll
        for (int ni = 0; ni < 2; ni++) {
            if (SCALEOUT) {
#pragma unroll
                for (int e = 0; e < cfr[mi][ni].num_elements; e++) cfr[mi][ni].x[e] *= SCALE_;
            }
            wmma::store_matrix_sync(
                C + (size_t)(bm * 128 + wm * 64 + mi * 16) * ldc + bn * 128 + wn * 32 + ni * 16,
                cfr[mi][ni], ldc, wmma::mem_row_major);
        }
}

// ---------------- GEMM wrapper kernels (R1 launch shapes) ----------------
__global__ __launch_bounds__(256) void k_qkv(
    const float* __restrict__ hs, const float* __restrict__ w,
    const float* __restrict__ lora_out)
{
    const int b = (int)(blockIdx.y >> 3);
    gemm_wmma_core<0, 1, 0>(hs, HID_, w, HID_, g_qkv, O3_, HID_,
                            blockIdx.y, blockIdx.x,
                            g_mid, lora_out + (size_t)b * O3_ * R_);
}

__global__ __launch_bounds__(256) void k_scores()
{
    if (blockIdx.x > blockIdx.y) return;
    const size_t z = blockIdx.z;
    gemm_wmma_core<0, 0, 1>(g_q + z * S_ * HD_, HD_, g_k + z * S_ * HD_, HD_,
                            g_scores + z * S_ * S_, S_, HD_,
                            blockIdx.y, blockIdx.x, nullptr, nullptr);
}

__global__ __launch_bounds__(256) void k_pv()
{
    const size_t z = blockIdx.y;
    const int b = (int)(z >> 5), h = (int)(z & 31);
    const int bm = (int)blockIdx.x;
    const int klim = (bm + 1) * 128;
    gemm_wmma_core<1, 0, 0>(g_scores + z * S_ * S_, S_,
                            g_qkv + (size_t)b * S_ * O3_ + 2 * HID_ + h * HD_, O3_,
                            g_attn + (size_t)b * S_ * HID_ + h * HD_, HID_,
                            klim, bm, 0, nullptr, nullptr);
}

__global__ __launch_bounds__(256) void k_dense(
    const float* __restrict__ w, float* __restrict__ out)
{
    gemm_wmma_core<0, 0, 0>(g_attn, HID_, w, HID_, out, HID_, HID_,
                            blockIdx.y, blockIdx.x, nullptr, nullptr);
}

// ---------------- small kernels: VERBATIM from passing R1 ----------------
__global__ __launch_bounds__(256) void lora_mid_kernel(
    const float* __restrict__ hs, const float* __restrict__ lin)
{
    const int row = blockIdx.x;
    const int b = row / S_;
    __shared__ float sh[HID_];
    for (int i = threadIdx.x; i < HID_; i += 256) sh[i] = hs[(size_t)row * HID_ + i];
    __syncthreads();
    const int warp = threadIdx.x >> 5, lane = threadIdx.x & 31;
    for (int r = warp; r < R_; r += 8) {
        const float* lrow = lin + ((size_t)b * R_ + r) * HID_;
        float acc = 0.f;
        for (int i = lane; i < HID_; i += 32) acc = fmaf(sh[i], lrow[i], acc);
#pragma unroll
        for (int o = 16; o > 0; o >>= 1) acc += __shfl_xor_sync(0xffffffffu, acc, o);
        if (lane == 0) g_mid[(size_t)row * R_ + r] = acc;
    }
}

__global__ __launch_bounds__(256) void rope_kernel(const int* __restrict__ positions)
{
    const int bs = blockIdx.x;
    const int b = bs / S_, s = bs % S_;
    __shared__ float cs[64], sn[64];
    if (threadIdx.x < 64) {
        float inv = powf(10000.f, -(float)threadIdx.x / 64.f);
        float f = (float)positions[s] * inv;
        cs[threadIdx.x] = cosf(f);
        sn[threadIdx.x] = sinf(f);
    }
    __syncthreads();
    const float* base = g_qkv + (size_t)bs * O3_;
    for (int t = threadIdx.x; t < NH_ * 64; t += 256) {
        int h = t >> 6, i = t & 63;
        float c = cs[i], sv = sn[i];
        size_t o = ((size_t)(b * NH_ + h) * S_ + s) * HD_;
        float x1 = base[h * HD_ + i], x2 = base[h * HD_ + 64 + i];
        g_q[o + i]      = x1 * c - x2 * sv;
        g_q[o + 64 + i] = x2 * c + x1 * sv;
        float y1 = base[HID_ + h * HD_ + i], y2 = base[HID_ + h * HD_ + 64 + i];
        g_k[o + i]      = y1 * c - y2 * sv;
        g_k[o + 64 + i] = y2 * c + y1 * sv;
    }
}

__global__ __launch_bounds__(256) void softmax_kernel()
{
    const size_t row = blockIdx.x;              // z*S + q
    const int q = (int)(row & (S_ - 1));
    float* p = g_scores + row * S_;
    const int n = q + 1;
    const int tid = threadIdx.x;
    __shared__ float red[8];

    float m = -1e30f;
    for (int i = tid; i < n; i += 256) m = fmaxf(m, p[i]);
#pragma unroll
    for (int o = 16; o > 0; o >>= 1) m = fmaxf(m, __shfl_xor_sync(0xffffffffu, m, o));
    if ((tid & 31) == 0) red[tid >> 5] = m;
    __syncthreads();
    float mm = red[0];
#pragma unroll
    for (int i = 1; i < 8; i++) mm = fmaxf(mm, red[i]);

    float sum = 0.f;
    for (int i = tid; i < n; i += 256) {
        float e = __expf(p[i] - mm);
        p[i] = e;
        sum += e;
    }
#pragma unroll
    for (int o = 16; o > 0; o >>= 1) sum += __shfl_xor_sync(0xffffffffu, sum, o);
    __syncthreads();
    if ((tid & 31) == 0) red[tid >> 5] = sum;
    __syncthreads();
    float tot = 0.f;
#pragma unroll
    for (int i = 0; i < 8; i++) tot += red[i];
    float inv = 1.f / tot;
    for (int i = tid; i < n; i += 256) p[i] *= inv;
    for (int i = n + tid; i < S_; i += 256) p[i] = 0.f;
}

// ---------------- launch (R1 structure) ----------------
extern "C" void kernel_launch(void* const* d_in, const int* in_sizes, int n_in,
                              void* d_out, int out_size)
{
    const int*   positions = (const int*)d_in[0];
    const float* hs        = (const float*)d_in[1];
    const float* w_qkv     = (const float*)d_in[2];
    const float* w_dense   = (const float*)d_in[3];
    const float* lora_in   = (const float*)d_in[4];
    const float* lora_out  = (const float*)d_in[5];
    float* out = (float*)d_out;

    lora_mid_kernel<<<Bb_ * S_, 256>>>(hs, lora_in);

    k_qkv<<<dim3(O3_ / 128, (Bb_ * S_) / 128), 256>>>(hs, w_qkv, lora_out);

    rope_kernel<<<Bb_ * S_, 256>>>(positions);

    k_scores<<<dim3(S_ / 128, S_ / 128, Bb_ * NH_), 256>>>();

    softmax_kernel<<<Bb_ * NH_ * S_, 256>>>();

    k_pv<<<dim3(S_ / 128, Bb_ * NH_), 256>>>();

    k_dense<<<dim3(HID_ / 128, (Bb_ * S_) / 128), 256>>>(w_dense, out);
}

// round 6
// speedup vs baseline: 2.1613x; 1.1429x over previous
#include <cuda_runtime.h>
#include <cuda_bf16.h>
#include <mma.h>
#include <math.h>
#include <stdint.h>
#include <type_traits>

using namespace nvcuda;

#define Bb_ 4
#define S_ 1024
#define HID_ 4096
#define NH_ 32
#define HD_ 128
#define O3_ 12288
#define R_ 32
#define SCALE_ 0.08838834764831845f

typedef __nv_bfloat16 bf16;

// ---- scratch: EXACTLY the R1/R5-proven buffer set (914 MB) ----
__device__ float g_qkv[(size_t)Bb_ * S_ * O3_];        // 201 MB
__device__ float g_mid[Bb_ * S_ * R_];
__device__ float g_q[(size_t)Bb_ * NH_ * S_ * HD_];    // 67 MB
__device__ float g_k[(size_t)Bb_ * NH_ * S_ * HD_];    // 67 MB
__device__ float g_scores[(size_t)Bb_ * NH_ * S_ * S_];// 512 MB
__device__ float g_attn[(size_t)Bb_ * S_ * HID_];      // 67 MB

__device__ __forceinline__ void split1(float x, bf16& h, bf16& l) {
    h = __float2bfloat16(x);
    l = __float2bfloat16(x - __bfloat162float(h));
}

__device__ __forceinline__ void split4store(float4 v, bf16* hp, bf16* lp) {
    bf16 h0, h1, h2, h3, l0, l1, l2, l3;
    split1(v.x, h0, l0); split1(v.y, h1, l1);
    split1(v.z, h2, l2); split1(v.w, h3, l3);
    __nv_bfloat162 a, b, c, d;
    a.x = h0; a.y = h1; b.x = h2; b.y = h3;
    c.x = l0; c.y = l1; d.x = l2; d.y = l3;
    *reinterpret_cast<__nv_bfloat162*>(hp)     = a;
    *reinterpret_cast<__nv_bfloat162*>(hp + 2) = b;
    *reinterpret_cast<__nv_bfloat162*>(lp)     = c;
    *reinterpret_cast<__nv_bfloat162*>(lp + 2) = d;
}

// ---------------- pipelined wmma split GEMM core ----------------
// C[m,n] = A[m,:].B'  where B' is B[n][k] (BROW=0, NT) or B[k][n] (BROW=1, NN).
// fp32 inputs split in-kernel to bf16 hi/lo; 3-term MMA; fp32 accum/output.
// Block 128x128, 8 warps (2x4), warp tile 64x32, BK=16.
// 2-stage smem double-buffer + register staging; ONE syncthreads per K-iter.
template <int BROW, int LORA, int SCALEOUT>
__device__ __forceinline__ void gemm_wmma_core(
    const float* __restrict__ A, const int lda,
    const float* __restrict__ B, const int ldb,
    float* __restrict__ C, const int ldc,
    const int klim, const int bm, const int bn,
    const float* __restrict__ mid, const float* __restrict__ lora)
{
    __shared__ __align__(16) bf16 smA[2][2][128][24];            // 24KB: [stage][hi/lo][m][k]
    constexpr int BSTG = BROW ? (16 * 136) : (128 * 24);         // per split-half
    __shared__ __align__(16) bf16 smB[2][2 * BSTG];              // 17KB or 24KB

    const int t = threadIdx.x;
    const int warp = t >> 5;
    const int wm = warp >> 2, wn = warp & 3;

    wmma::fragment<wmma::accumulator, 16, 16, 16, float> cfr[4][2];
#pragma unroll
    for (int mi = 0; mi < 4; mi++)
#pragma unroll
        for (int ni = 0; ni < 2; ni++) wmma::fill_fragment(cfr[mi][ni], 0.0f);

    const int kT = klim >> 4;
    const int total = kT + (LORA ? (R_ / 16) : 0);

    float4 rA[2], rB[2];

    auto loadT = [&](int tt) {
        const bool tail = LORA && (tt >= kT);
        const int k0 = tail ? ((tt - kT) << 4) : (tt << 4);
#pragma unroll
        for (int i = 0; i < 2; i++) {
            int idx = i * 256 + t;
            int row = idx >> 2, q4 = (idx & 3) * 4;
            const float* sA = tail
                ? (mid + (size_t)(bm * 128 + row) * R_ + k0 + q4)
                : (A + (size_t)(bm * 128 + row) * lda + k0 + q4);
            rA[i] = *reinterpret_cast<const float4*>(sA);
            if (!BROW) {
                const float* sB = tail
                    ? (lora + (size_t)(bn * 128 + row) * R_ + k0 + q4)
                    : (B + (size_t)(bn * 128 + row) * ldb + k0 + q4);
                rB[i] = *reinterpret_cast<const float4*>(sB);
            } else {
                int kr = idx >> 5, nc = (idx & 31) * 4;
                rB[i] = *reinterpret_cast<const float4*>(
                    B + (size_t)(k0 + kr) * ldb + bn * 128 + nc);
            }
        }
    };

    auto storeT = [&](int st) {
#pragma unroll
        for (int i = 0; i < 2; i++) {
            int idx = i * 256 + t;
            int row = idx >> 2, q4 = (idx & 3) * 4;
            split4store(rA[i], &smA[st][0][row][q4], &smA[st][1][row][q4]);
            if (!BROW) {
                split4store(rB[i], &smB[st][row * 24 + q4], &smB[st][BSTG + row * 24 + q4]);
            } else {
                int kr = idx >> 5, nc = (idx & 31) * 4;
                split4store(rB[i], &smB[st][kr * 136 + nc], &smB[st][BSTG + kr * 136 + nc]);
            }
        }
    };

    loadT(0);
    storeT(0);
    __syncthreads();

    using BLay = typename std::conditional<BROW != 0, wmma::row_major, wmma::col_major>::type;

    for (int tt = 0; tt < total; tt++) {
        if (tt + 1 < total) loadT(tt + 1);            // global loads in flight over compute
        const int st = tt & 1;

        wmma::fragment<wmma::matrix_b, 16, 16, 16, bf16, BLay> bH[2], bL[2];
#pragma unroll
        for (int ni = 0; ni < 2; ni++) {
            if (BROW) {
                wmma::load_matrix_sync(bH[ni], &smB[st][wn * 32 + ni * 16], 136);
                wmma::load_matrix_sync(bL[ni], &smB[st][BSTG + wn * 32 + ni * 16], 136);
            } else {
                wmma::load_matrix_sync(bH[ni], &smB[st][(wn * 32 + ni * 16) * 24], 24);
                wmma::load_matrix_sync(bL[ni], &smB[st][BSTG + (wn * 32 + ni * 16) * 24], 24);
            }
        }
#pragma unroll
        for (int mi = 0; mi < 4; mi++) {
            wmma::fragment<wmma::matrix_a, 16, 16, 16, bf16, wmma::row_major> aH, aL;
            wmma::load_matrix_sync(aH, &smA[st][0][wm * 64 + mi * 16][0], 24);
            wmma::load_matrix_sync(aL, &smA[st][1][wm * 64 + mi * 16][0], 24);
#pragma unroll
            for (int ni = 0; ni < 2; ni++) {
                wmma::mma_sync(cfr[mi][ni], aH, bH[ni], cfr[mi][ni]);
                wmma::mma_sync(cfr[mi][ni], aH, bL[ni], cfr[mi][ni]);
                wmma::mma_sync(cfr[mi][ni], aL, bH[ni], cfr[mi][ni]);
            }
        }
        if (tt + 1 < total) storeT((tt + 1) & 1);     // write the opposite buffer
        __syncthreads();
    }

#pragma unroll
    for (int mi = 0; mi < 4; mi++)
#pragma unroll
        for (int ni = 0; ni < 2; ni++) {
            if (SCALEOUT) {
#pragma unroll
                for (int e = 0; e < cfr[mi][ni].num_elements; e++) cfr[mi][ni].x[e] *= SCALE_;
            }
            wmma::store_matrix_sync(
                C + (size_t)(bm * 128 + wm * 64 + mi * 16) * ldc + bn * 128 + wn * 32 + ni * 16,
                cfr[mi][ni], ldc, wmma::mem_row_major);
        }
}

// ---------------- GEMM wrapper kernels ----------------
__global__ __launch_bounds__(256, 2) void k_qkv(
    const float* __restrict__ hs, const float* __restrict__ w,
    const float* __restrict__ lora_out)
{
    const int b = (int)(blockIdx.y >> 3);
    gemm_wmma_core<0, 1, 0>(hs, HID_, w, HID_, g_qkv, O3_, HID_,
                            blockIdx.y, blockIdx.x,
                            g_mid, lora_out + (size_t)b * O3_ * R_);
}

__global__ __launch_bounds__(256, 2) void k_scores()
{
    if (blockIdx.x > blockIdx.y) return;
    const size_t z = blockIdx.z;
    gemm_wmma_core<0, 0, 1>(g_q + z * S_ * HD_, HD_, g_k + z * S_ * HD_, HD_,
                            g_scores + z * S_ * S_, S_, HD_,
                            blockIdx.y, blockIdx.x, nullptr, nullptr);
}

__global__ __launch_bounds__(256, 2) void k_pv()
{
    const size_t z = blockIdx.y;
    const int b = (int)(z >> 5), h = (int)(z & 31);
    const int bm = (int)blockIdx.x;
    const int klim = (bm + 1) * 128;
    gemm_wmma_core<1, 0, 0>(g_scores + z * S_ * S_, S_,
                            g_qkv + (size_t)b * S_ * O3_ + 2 * HID_ + h * HD_, O3_,
                            g_attn + (size_t)b * S_ * HID_ + h * HD_, HID_,
                            klim, bm, 0, nullptr, nullptr);
}

__global__ __launch_bounds__(256, 2) void k_dense(
    const float* __restrict__ w, float* __restrict__ out)
{
    gemm_wmma_core<0, 0, 0>(g_attn, HID_, w, HID_, out, HID_, HID_,
                            blockIdx.y, blockIdx.x, nullptr, nullptr);
}

// ---------------- small kernels: VERBATIM from passing R5 ----------------
__global__ __launch_bounds__(256) void lora_mid_kernel(
    const float* __restrict__ hs, const float* __restrict__ lin)
{
    const int row = blockIdx.x;
    const int b = row / S_;
    __shared__ float sh[HID_];
    for (int i = threadIdx.x; i < HID_; i += 256) sh[i] = hs[(size_t)row * HID_ + i];
    __syncthreads();
    const int warp = threadIdx.x >> 5, lane = threadIdx.x & 31;
    for (int r = warp; r < R_; r += 8) {
        const float* lrow = lin + ((size_t)b * R_ + r) * HID_;
        float acc = 0.f;
        for (int i = lane; i < HID_; i += 32) acc = fmaf(sh[i], lrow[i], acc);
#pragma unroll
        for (int o = 16; o > 0; o >>= 1) acc += __shfl_xor_sync(0xffffffffu, acc, o);
        if (lane == 0) g_mid[(size_t)row * R_ + r] = acc;
    }
}

__global__ __launch_bounds__(256) void rope_kernel(const int* __restrict__ positions)
{
    const int bs = blockIdx.x;
    const int b = bs / S_, s = bs % S_;
    __shared__ float cs[64], sn[64];
    if (threadIdx.x < 64) {
        float inv = powf(10000.f, -(float)threadIdx.x / 64.f);
        float f = (float)positions[s] * inv;
        cs[threadIdx.x] = cosf(f);
        sn[threadIdx.x] = sinf(f);
    }
    __syncthreads();
    const float* base = g_qkv + (size_t)bs * O3_;
    for (int t = threadIdx.x; t < NH_ * 64; t += 256) {
        int h = t >> 6, i = t & 63;
        float c = cs[i], sv = sn[i];
        size_t o = ((size_t)(b * NH_ + h) * S_ + s) * HD_;
        float x1 = base[h * HD_ + i], x2 = base[h * HD_ + 64 + i];
        g_q[o + i]      = x1 * c - x2 * sv;
        g_q[o + 64 + i] = x2 * c + x1 * sv;
        float y1 = base[HID_ + h * HD_ + i], y2 = base[HID_ + h * HD_ + 64 + i];
        g_k[o + i]      = y1 * c - y2 * sv;
        g_k[o + 64 + i] = y2 * c + y1 * sv;
    }
}

__global__ __launch_bounds__(256) void softmax_kernel()
{
    const size_t row = blockIdx.x;              // z*S + q
    const int q = (int)(row & (S_ - 1));
    float* p = g_scores + row * S_;
    const int n = q + 1;
    const int tid = threadIdx.x;
    __shared__ float red[8];

    float m = -1e30f;
    for (int i = tid; i < n; i += 256) m = fmaxf(m, p[i]);
#pragma unroll
    for (int o = 16; o > 0; o >>= 1) m = fmaxf(m, __shfl_xor_sync(0xffffffffu, m, o));
    if ((tid & 31) == 0) red[tid >> 5] = m;
    __syncthreads();
    float mm = red[0];
#pragma unroll
    for (int i = 1; i < 8; i++) mm = fmaxf(mm, red[i]);

    float sum = 0.f;
    for (int i = tid; i < n; i += 256) {
        float e = __expf(p[i] - mm);
        p[i] = e;
        sum += e;
    }
#pragma unroll
    for (int o = 16; o > 0; o >>= 1) sum += __shfl_xor_sync(0xffffffffu, sum, o);
    __syncthreads();
    if ((tid & 31) == 0) red[tid >> 5] = sum;
    __syncthreads();
    float tot = 0.f;
#pragma unroll
    for (int i = 0; i < 8; i++) tot += red[i];
    float inv = 1.f / tot;
    for (int i = tid; i < n; i += 256) p[i] *= inv;
    for (int i = n + tid; i < S_; i += 256) p[i] = 0.f;
}

// ---------------- launch ----------------
extern "C" void kernel_launch(void* const* d_in, const int* in_sizes, int n_in,
                              void* d_out, int out_size)
{
    const int*   positions = (const int*)d_in[0];
    const float* hs        = (const float*)d_in[1];
    const float* w_qkv     = (const float*)d_in[2];
    const float* w_dense   = (const float*)d_in[3];
    const float* lora_in   = (const float*)d_in[4];
    const float* lora_out  = (const float*)d_in[5];
    float* out = (float*)d_out;

    lora_mid_kernel<<<Bb_ * S_, 256>>>(hs, lora_in);

    k_qkv<<<dim3(O3_ / 128, (Bb_ * S_) / 128), 256>>>(hs, w_qkv, lora_out);

    rope_kernel<<<Bb_ * S_, 256>>>(positions);

    k_scores<<<dim3(S_ / 128, S_ / 128, Bb_ * NH_), 256>>>();

    softmax_kernel<<<Bb_ * NH_ * S_, 256>>>();

    k_pv<<<dim3(S_ / 128, Bb_ * NH_), 256>>>();

    k_dense<<<dim3(HID_ / 128, (Bb_ * S_) / 128), 256>>>(w_dense, out);
}